// round 17
// baseline (speedup 1.0000x reference)
#include <cuda_runtime.h>
#include <utility>
#include <math.h>

// =====================================================================
// HiPPO-LegS reconstruction:  out = F(x),  x = 2*t/curr_t - 1.
// Piecewise-cubic table indexed by w = sqrt(1-|x|) (sign-split halves,
// uniform phase coverage, no acosf) -- validated R16, rel_err 4.4e-5.
//
// R17: latency-hiding rebuild of the fused kernel:
//  - NO smem staging: gathers hit the 32KB global table via __ldg
//    (L1-resident; kills 16MB of L2 staging traffic + a barrier)
//  - EV_V=2, TPB=256, 1024 blocks -> 55 warps/SM (was 27.7): the spin
//    only depends on builder blocks 0..31 (wave-1 guaranteed), so
//    multi-wave grids are deadlock-free
//  - eval indices computed BEFORE the spin (overlaps builder wait)
// Builders: 32 blocks sample F at 4 Chebyshev nodes/interval (forward
// Legendre recurrence, all-float, compile-time node table) + constexpr
// 4x4 fit -> 32KB table; counter + threadfence; last block resets.
// =====================================================================

#define NDEG  256
#define MHALF 1024               // intervals per half
#define M_IV  (2 * MHALF)        // 2048 total
#define NNODE 4
#define TPB   256
#define IVB   (TPB / 4)          // 64 intervals per builder chunk
#define NCHUNK (M_IV / IVB)      // 32 chunks
#define EV_V  2

static constexpr double PI_D = 3.14159265358979323846;

// ---------------- constexpr helpers ----------------

__host__ __device__ constexpr double csqrt(double v) {
    double g = v < 1.0 ? 1.0 : v;
    for (int i = 0; i < 100; ++i) g = 0.5 * (g + v / g);
    return g;
}

__host__ __device__ constexpr double ccos(double x) {
    while (x >  PI_D) x -= 2.0 * PI_D;
    while (x < -PI_D) x += 2.0 * PI_D;
    double x2 = x * x, term = 1.0, sum = 0.0;
    for (int m = 0; m < 18; ++m) {
        sum += term;
        term *= -x2 / ((2.0 * m + 1.0) * (2.0 * m + 2.0));
    }
    return sum;
}

// sqrt(2m+1) table
struct SQT { float v[NDEG + 2]; };
template <size_t... I>
constexpr SQT make_sq(std::index_sequence<I...>) {
    return SQT{{ ((float)csqrt(2.0 * (double)I + 1.0))... }};
}
__constant__ SQT SQ = make_sq(std::make_index_sequence<NDEG + 2>{});

// node x table: interval J = h*MHALF + jj (h=0: x>=0, h=1: x<0),
// node i: w = (jj + 0.5 + 0.5*u_i)/MHALF, x = (h==0) ? 1-w^2 : w^2-1
__host__ __device__ constexpr float xnode_of(int gid) {
    int J = gid / NNODE, node = gid % NNODE;
    int h = J / MHALF, jj = J % MHALF;
    double u = ccos(PI_D * (2 * node + 1) / 8.0);
    double w = (jj + 0.5 + 0.5 * u) / (double)MHALF;
    double x = (h == 0) ? (1.0 - w * w) : (w * w - 1.0);
    return (float)x;
}
struct XT { float v[M_IV * NNODE]; };
template <size_t... I>
constexpr XT make_xn(std::index_sequence<I...>) {
    return XT{{ xnode_of((int)I)... }};
}
__device__ const XT g_xn = make_xn(std::make_index_sequence<M_IV * NNODE>{});

// W4[q][i]: samples at 4 Chebyshev nodes -> monomial coeffs (float)
struct W4T { float w[NNODE][NNODE]; };
__host__ __device__ constexpr W4T make_W4() {
    W4T r{};
    for (int i = 0; i < NNODE; ++i) {
        double c[4] = {0.0, 0.0, 0.0, 0.0};
        for (int p = 0; p < 4; ++p) {
            double kp = (p == 0) ? 0.25 : 0.5;
            c[p] = kp * ccos(p * PI_D * (2 * i + 1) / 8.0);
        }
        r.w[0][i] = (float)(c[0] - c[2]);
        r.w[1][i] = (float)(c[1] - 3.0 * c[3]);
        r.w[2][i] = (float)(2.0 * c[2]);
        r.w[3][i] = (float)(4.0 * c[3]);
    }
    return r;
}
__constant__ W4T W4 = make_W4();

// ---------------- device scratch (static: no allocation) ----------------

__device__ __align__(16) float g_rec[M_IV * 4];   // 32 KB coeff table
__device__ volatile int g_done;
__device__ int g_exit;

// ---------------- fused kernel ----------------

__global__ __launch_bounds__(TPB) void hippo_fused(
    const float* __restrict__ t, const float* __restrict__ coef,
    const int* __restrict__ ctp, float* __restrict__ out, int n)
{
    __shared__ float4 tab[NDEG];                  // 4 KB (build only)
    __shared__ float  s_smp[IVB][NNODE];          // 1 KB (build only)

    const int tid = threadIdx.x;

    // ---- hoisted input loads ----
    const long long base = ((long long)blockIdx.x * TPB + tid) * EV_V;
    bool active = (base < n);
    bool full   = (base + EV_V <= n);
    float tv[EV_V] = {0.f, 0.f};
    if (active) {
        if (full) {
            float2 ta = *reinterpret_cast<const float2*>(t + base);
            tv[0] = ta.x; tv[1] = ta.y;
        } else {
#pragma unroll
            for (int v = 0; v < EV_V; ++v) {
                long long idx = base + v;
                tv[v] = (idx < n) ? t[idx] : 0.0f;
            }
        }
    }
    float ct = 1.0f;
    if (ctp) {
        int iv   = *ctp;
        float fv = __int_as_float(iv);
        ct = (iv > 0 && iv < (1 << 20)) ? (float)iv : fv;
    }

    // ---------------- phase A: build (first NCHUNK blocks) --------------
    const int nb = (gridDim.x < NCHUNK) ? (int)gridDim.x : NCHUNK;
    if ((int)blockIdx.x < nb) {
        for (int k = tid; k < NDEG; k += TPB) {
            float a = 0.0f, b = 0.0f;
            if (k >= 1) {
                a = (2.0f * k + 1.0f) / (float)(k + 1);
                b = -(float)k / (float)(k + 1);
            }
            float w = SQ.v[k + 1] * __ldg(coef + k);   // w_{k+1}
            tab[k] = make_float4(a, b, w, 0.0f);
        }
        __syncthreads();

        const int iv   = tid >> 2;                // 0..IVB-1
        const int node = tid & 3;

        for (int cb = blockIdx.x; cb < NCHUNK; cb += gridDim.x) {
            const int J = cb * IVB + iv;
            float x = __ldg(&g_xn.v[J * NNODE + node]);

            float pm1 = 1.0f, p = x;
            float acc = tab[0].z * x;             // w_1 * P_1
#pragma unroll 8
            for (int k = 1; k < NDEG; ++k) {
                float4 q  = tab[k];
                float  pn = fmaf(q.x * x, p, q.y * pm1);
                acc = fmaf(q.z, pn, acc);
                pm1 = p; p = pn;
            }
            s_smp[iv][node] = acc;
            __syncthreads();

            float a = 0.0f;
#pragma unroll
            for (int i = 0; i < NNODE; ++i)
                a = fmaf(W4.w[node][i], s_smp[iv][i], a);
            g_rec[J * 4 + node] = a;
            __syncthreads();
        }
        __threadfence();
        if (tid == 0) atomicAdd((int*)&g_done, 1);
    }

    // ---------------- precompute eval indices (overlaps builder wait) ---
    const float sc2 = 2.0f / ct;
    int   idx_r[EV_V];
    float u_r[EV_V];
#pragma unroll
    for (int v = 0; v < EV_V; ++v) {
        float x  = fmaf(tv[v], sc2, -1.0f);
        float ax = fminf(fabsf(x), 1.0f);
        float y  = 1.0f - ax;                 // exact for ax >= 0.5
        float w  = sqrtf(y);
        int   j  = (int)(w * (float)MHALF);
        j = min(j, MHALF - 1);
        u_r[v]   = fmaf(w, 2.0f * (float)MHALF, -(float)(2 * j + 1));
        idx_r[v] = j + ((x < 0.0f) ? MHALF : 0);
    }

    // ---------------- phase B: global wait ----------------
    if (tid == 0) {
        while (g_done < nb) __nanosleep(64);
    }
    __syncthreads();
    __threadfence();   // acquire: order table reads after the flag

    // ---------------- phase C: evaluate (direct __ldg gathers) ----------
    if (active) {
        const float4* __restrict__ rec =
            reinterpret_cast<const float4*>(g_rec);
        float res[EV_V];
#pragma unroll
        for (int v = 0; v < EV_V; ++v) {
            float4 m = __ldg(rec + idx_r[v]);     // L1-resident 32 KB table
            float  u = u_r[v];
            res[v] = fmaf(fmaf(fmaf(m.w, u, m.z), u, m.y), u, m.x);
        }

        if (full) {
            *reinterpret_cast<float2*>(out + base) =
                make_float2(res[0], res[1]);
        } else {
#pragma unroll
            for (int v = 0; v < EV_V; ++v) {
                long long idx = base + v;
                if (idx < n) out[idx] = res[v];
            }
        }
    }

    // ---------------- phase D: last-block reset (replay determinism) ----
    __syncthreads();
    if (tid == 0) {
        int prev = atomicAdd(&g_exit, 1);
        if (prev == (int)gridDim.x - 1) {
            g_exit = 0;
            g_done = 0;
            __threadfence();
        }
    }
}

// ---------------- launch ----------------

extern "C" void kernel_launch(void* const* d_in, const int* in_sizes, int n_in,
                              void* d_out, int out_size)
{
    // Identify inputs by size: big -> t, 1 -> curr_t, remaining -> coef
    int ti = -1, ci = -1, si = -1;
    for (int i = 0; i < n_in; ++i) {
        if (in_sizes[i] == out_size && ti < 0)      ti = i;
        else if (in_sizes[i] == 1 && si < 0)        si = i;
        else if (ci < 0)                            ci = i;
    }
    if (ti < 0) ti = 0;
    if (ci < 0) ci = (n_in > 1 ? 1 : 0);

    const float* t    = (const float*)d_in[ti];
    const float* coef = (const float*)d_in[ci];
    const int*   ct   = (si >= 0) ? (const int*)d_in[si] : nullptr;

    int n = out_size;
    int epb    = TPB * EV_V;                      // 512 elems/block
    int blocks = (n + epb - 1) / epb;             // 1024 for n=524288
    hippo_fused<<<blocks, TPB>>>(t, coef, ct, (float*)d_out, n);
}